// round 4
// baseline (speedup 1.0000x reference)
#include <cuda_runtime.h>
#include <stdint.h>

// ---------------------------------------------------------------------------
// Fused Instant-NGP forward, round 4:
//  - all wide MLP layers use packed fma.rn.f32x2 (FFMA2): 2 MACs/issue
//  - weights in __constant__, read as 128-bit LDCU (ulonglong2 = 2 packed ops)
//  - hash encode phase produces packed (a0,a1) per level, all gathers batched
//  - h1 computed in two 32-wide halves to bound register pressure
// ---------------------------------------------------------------------------

#define THASH 524288u
#define THASH_MASK (THASH - 1u)
#define PI2 2654435761u
#define PI3 805459861u

// constant-weight layout (floats, 16B-aligned chunks)
#define OW1 0        // [32,64]
#define OB1 2048
#define OW2 2112     // [64,16]
#define OB2 3136
#define OW3 3152     // [43,64]
#define OB3 5904
#define OW4 5968     // [64,64]
#define OB4 10064
#define OW5 10128    // [64,3]
#define OB5 10320
#define WTOT 10324

__constant__ __align__(16) float cw[WTOT];

#define QIX(fo) ((fo) >> 2)   // float-offset -> ulonglong2 index

typedef unsigned long long u64t;

__device__ __forceinline__ u64t pk2(float lo, float hi) {
    u64t r; asm("mov.b64 %0, {%1,%2};" : "=l"(r) : "f"(lo), "f"(hi)); return r;
}
__device__ __forceinline__ void upk2(u64t v, float& lo, float& hi) {
    asm("mov.b64 {%0,%1}, %2;" : "=f"(lo), "=f"(hi) : "l"(v));
}
__device__ __forceinline__ u64t fma2(u64t a, u64t b, u64t c) {
    u64t d; asm("fma.rn.f32x2 %0, %1, %2, %3;" : "=l"(d) : "l"(a), "l"(b), "l"(c)); return d;
}

__global__ void __launch_bounds__(128, 4)
ngp_fused_kernel(const float* __restrict__ gx, const float* __restrict__ gd,
                 const float* __restrict__ tables,
                 float* __restrict__ out_color, float* __restrict__ out_sigma,
                 int N)
{
    const ulonglong2* cwq = reinterpret_cast<const ulonglong2*>(cw);
    const u64t*       cwp = reinterpret_cast<const u64t*>(cw);

    int n = blockIdx.x * blockDim.x + threadIdx.x;
    if (n >= N) return;

    // ---- position, AABB mask, [0,1) coords ----
    float px = gx[3 * n + 0] * (1.0f / 3.0f);
    float py = gx[3 * n + 1] * (1.0f / 3.0f);
    float pz = gx[3 * n + 2] * (1.0f / 3.0f);
    bool mask = (fabsf(px) < 0.5f) && (fabsf(py) < 0.5f) && (fabsf(pz) < 0.5f);
    const float HI = 1.0f - 1e-7f;
    float x0 = fminf(fmaxf(px + 0.5f, 0.0f), HI);
    float x1 = fminf(fmaxf(py + 0.5f, 0.0f), HI);
    float x2 = fminf(fmaxf(pz + 0.5f, 0.0f), HI);

    // ---- Phase A: hash encode all 16 levels -> packed (a0,a1) ----
    const float resf[16] = {16.f,22.f,30.f,42.f,58.f,80.f,110.f,152.f,
                            210.f,290.f,400.f,552.f,762.f,1052.f,1452.f,2004.f};
    u64t fpk[16];
    #pragma unroll
    for (int l = 0; l < 16; l++) {
        float res = resf[l];
        float s0 = x0 * res, s1 = x1 * res, s2 = x2 * res;
        float f0 = floorf(s0), f1 = floorf(s1), f2 = floorf(s2);
        float t0 = s0 - f0, t1 = s1 - f1, t2 = s2 - f2;
        float u0 = 1.0f - t0, u1 = 1.0f - t1, u2 = 1.0f - t2;
        uint32_t i0 = (uint32_t)f0, i1 = (uint32_t)f1, i2 = (uint32_t)f2;
        const float2* tab2 = reinterpret_cast<const float2*>(tables) + (size_t)l * (size_t)THASH;
        const float4* tab4 = reinterpret_cast<const float4*>(tab2);

        uint32_t hy0 = i1 * PI2, hy1 = (i1 + 1u) * PI2;
        uint32_t hz0 = i2 * PI3, hz1 = (i2 + 1u) * PI3;
        bool even = (i0 & 1u) == 0u;

        float a0 = 0.0f, a1 = 0.0f;
        #pragma unroll
        for (int cyz = 0; cyz < 4; cyz++) {
            uint32_t hyz = ((cyz & 1) ? hy1 : hy0) ^ ((cyz & 2) ? hz1 : hz0);
            float wyz = ((cyz & 1) ? t1 : u1) * ((cyz & 2) ? t2 : u2);
            uint32_t ia = (i0 ^ hyz) & THASH_MASK;
            float ax, ay, bx, by;
            if (even) {
                float4 g = __ldg(tab4 + (ia >> 1));
                bool lo = (ia & 1u) == 0u;
                ax = lo ? g.x : g.z; ay = lo ? g.y : g.w;
                bx = lo ? g.z : g.x; by = lo ? g.w : g.y;
            } else {
                uint32_t ib = ((i0 + 1u) ^ hyz) & THASH_MASK;
                float2 ga = __ldg(tab2 + ia);
                float2 gb = __ldg(tab2 + ib);
                ax = ga.x; ay = ga.y; bx = gb.x; by = gb.y;
            }
            float wa = wyz * u0, wb = wyz * t0;
            a0 = fmaf(wa, ax, fmaf(wb, bx, a0));
            a1 = fmaf(wa, ay, fmaf(wb, by, a1));
        }
        fpk[l] = pk2(a0, a1);
    }

    // ---- Phase B: h1 (two 32-wide halves), relu, fold into h2 ----
    u64t h2p[8];  // 16 outputs packed
    #pragma unroll
    for (int j = 0; j < 8; j++) h2p[j] = cwp[(OB2 >> 1) + j];

    #pragma unroll
    for (int half = 0; half < 2; half++) {
        const int hb = 32 * half;
        u64t hp[16];  // 32 outputs packed
        #pragma unroll
        for (int j = 0; j < 8; j++) {
            ulonglong2 b = cwq[QIX(OB1 + hb) + j];
            hp[2*j] = b.x; hp[2*j+1] = b.y;
        }
        #pragma unroll
        for (int l = 0; l < 16; l++) {
            float a0, a1; upk2(fpk[l], a0, a1);
            u64t a0p = pk2(a0, a0), a1p = pk2(a1, a1);
            const int q0 = QIX(OW1 + (2*l)   * 64 + hb);
            const int q1 = QIX(OW1 + (2*l+1) * 64 + hb);
            #pragma unroll
            for (int j = 0; j < 8; j++) {
                ulonglong2 u = cwq[q0 + j];
                ulonglong2 v = cwq[q1 + j];
                hp[2*j]   = fma2(a0p, u.x, fma2(a1p, v.x, hp[2*j]));
                hp[2*j+1] = fma2(a0p, u.y, fma2(a1p, v.y, hp[2*j+1]));
            }
        }
        // relu + fold into h2: h2 += relu(h1[k]) * w2[k,:]
        #pragma unroll
        for (int j = 0; j < 16; j++) {
            float lo, hi; upk2(hp[j], lo, hi);
            lo = fmaxf(lo, 0.0f); hi = fmaxf(hi, 0.0f);
            const int k0 = hb + 2*j;
            u64t lop = pk2(lo, lo), hip = pk2(hi, hi);
            const int qa = QIX(OW2 + k0 * 16);
            const int qb = QIX(OW2 + (k0 + 1) * 16);
            #pragma unroll
            for (int m = 0; m < 4; m++) {
                ulonglong2 u = cwq[qa + m];
                h2p[2*m]   = fma2(lop, u.x, h2p[2*m]);
                h2p[2*m+1] = fma2(lop, u.y, h2p[2*m+1]);
            }
            #pragma unroll
            for (int m = 0; m < 4; m++) {
                ulonglong2 u = cwq[qb + m];
                h2p[2*m]   = fma2(hip, u.x, h2p[2*m]);
                h2p[2*m+1] = fma2(hip, u.y, h2p[2*m+1]);
            }
        }
    }

    float h2s[16];
    #pragma unroll
    for (int j = 0; j < 8; j++) upk2(h2p[j], h2s[2*j], h2s[2*j+1]);

    out_sigma[n] = mask ? h2s[0] : -100000.0f;

    // ---- Phase C: c1 = relu(b3 + [dir(27)|h2(16)] @ w3), packed, streamed ----
    u64t c1p[32];
    #pragma unroll
    for (int j = 0; j < 16; j++) {
        ulonglong2 b = cwq[QIX(OB3) + j];
        c1p[2*j] = b.x; c1p[2*j+1] = b.y;
    }

    float dv[3];
    dv[0] = gd[3 * n + 0]; dv[1] = gd[3 * n + 1]; dv[2] = gd[3 * n + 2];

    #define C1_ACC(row, val) do {                                             \
        float _f = (val);                                                     \
        u64t _fp = pk2(_f, _f);                                               \
        const int _q = QIX(OW3 + (row) * 64);                                 \
        _Pragma("unroll")                                                     \
        for (int j = 0; j < 16; j++) {                                        \
            ulonglong2 u = cwq[_q + j];                                       \
            c1p[2*j]   = fma2(_fp, u.x, c1p[2*j]);                            \
            c1p[2*j+1] = fma2(_fp, u.y, c1p[2*j+1]);                          \
        }                                                                     \
    } while (0)

    C1_ACC(0, dv[0]);
    C1_ACC(1, dv[1]);
    C1_ACC(2, dv[2]);
    #pragma unroll
    for (int dim = 0; dim < 3; dim++) {
        #pragma unroll
        for (int f = 0; f < 4; f++) {
            float ang = dv[dim] * (float)(1 << f);
            float s, c;
            __sincosf(ang, &s, &c);
            C1_ACC(3  + dim * 4 + f, s);
            C1_ACC(15 + dim * 4 + f, c);
        }
    }
    #pragma unroll
    for (int j = 0; j < 16; j++) C1_ACC(27 + j, h2s[j]);
    #undef C1_ACC

    // relu c1 -> scalar array
    float c1s[64];
    #pragma unroll
    for (int j = 0; j < 32; j++) {
        float lo, hi; upk2(c1p[j], lo, hi);
        c1s[2*j]   = fmaxf(lo, 0.0f);
        c1s[2*j+1] = fmaxf(hi, 0.0f);
    }

    // ---- Phase D: c2 = relu(c1 @ w4 + b4) in 32-wide halves -> col ----
    float col[3];
    col[0] = cw[OB5 + 0]; col[1] = cw[OB5 + 1]; col[2] = cw[OB5 + 2];

    #pragma unroll
    for (int half = 0; half < 2; half++) {
        const int hb = 32 * half;
        u64t c2p[16];
        #pragma unroll
        for (int j = 0; j < 8; j++) {
            ulonglong2 b = cwq[QIX(OB4 + hb) + j];
            c2p[2*j] = b.x; c2p[2*j+1] = b.y;
        }
        #pragma unroll
        for (int k = 0; k < 64; k++) {
            u64t fp = pk2(c1s[k], c1s[k]);
            const int q = QIX(OW4 + k * 64 + hb);
            #pragma unroll
            for (int j = 0; j < 8; j++) {
                ulonglong2 u = cwq[q + j];
                c2p[2*j]   = fma2(fp, u.x, c2p[2*j]);
                c2p[2*j+1] = fma2(fp, u.y, c2p[2*j+1]);
            }
        }
        #pragma unroll
        for (int j = 0; j < 16; j++) {
            float lo, hi; upk2(c2p[j], lo, hi);
            lo = fmaxf(lo, 0.0f); hi = fmaxf(hi, 0.0f);
            const int k0 = hb + 2*j;
            col[0] = fmaf(lo, cw[OW5 + k0*3 + 0], col[0]);
            col[1] = fmaf(lo, cw[OW5 + k0*3 + 1], col[1]);
            col[2] = fmaf(lo, cw[OW5 + k0*3 + 2], col[2]);
            col[0] = fmaf(hi, cw[OW5 + (k0+1)*3 + 0], col[0]);
            col[1] = fmaf(hi, cw[OW5 + (k0+1)*3 + 1], col[1]);
            col[2] = fmaf(hi, cw[OW5 + (k0+1)*3 + 2], col[2]);
        }
    }

    #pragma unroll
    for (int j = 0; j < 3; j++) {
        float v = 1.0f / (1.0f + __expf(-col[j]));
        out_color[3 * n + j] = mask ? v : 0.0f;
    }
}

extern "C" void kernel_launch(void* const* d_in, const int* in_sizes, int n_in,
                              void* d_out, int out_size)
{
    const float* x      = (const float*)d_in[0];
    const float* d      = (const float*)d_in[1];
    const float* tables = (const float*)d_in[2];

    // copy weights into constant memory (D2D, graph-capturable)
    cudaMemcpyToSymbolAsync(cw, d_in[3],  2048 * 4, (size_t)OW1 * 4, cudaMemcpyDeviceToDevice, 0);
    cudaMemcpyToSymbolAsync(cw, d_in[4],    64 * 4, (size_t)OB1 * 4, cudaMemcpyDeviceToDevice, 0);
    cudaMemcpyToSymbolAsync(cw, d_in[5],  1024 * 4, (size_t)OW2 * 4, cudaMemcpyDeviceToDevice, 0);
    cudaMemcpyToSymbolAsync(cw, d_in[6],    16 * 4, (size_t)OB2 * 4, cudaMemcpyDeviceToDevice, 0);
    cudaMemcpyToSymbolAsync(cw, d_in[7],  2752 * 4, (size_t)OW3 * 4, cudaMemcpyDeviceToDevice, 0);
    cudaMemcpyToSymbolAsync(cw, d_in[8],    64 * 4, (size_t)OB3 * 4, cudaMemcpyDeviceToDevice, 0);
    cudaMemcpyToSymbolAsync(cw, d_in[9],  4096 * 4, (size_t)OW4 * 4, cudaMemcpyDeviceToDevice, 0);
    cudaMemcpyToSymbolAsync(cw, d_in[10],   64 * 4, (size_t)OB4 * 4, cudaMemcpyDeviceToDevice, 0);
    cudaMemcpyToSymbolAsync(cw, d_in[11],  192 * 4, (size_t)OW5 * 4, cudaMemcpyDeviceToDevice, 0);
    cudaMemcpyToSymbolAsync(cw, d_in[12],    3 * 4, (size_t)OB5 * 4, cudaMemcpyDeviceToDevice, 0);

    int N = in_sizes[0] / 3;
    float* out       = (float*)d_out;
    float* out_color = out;                   // [N,3]
    float* out_sigma = out + 3 * (size_t)N;   // [N]

    int block = 128;
    int grid  = (N + block - 1) / block;
    ngp_fused_kernel<<<grid, block>>>(x, d, tables, out_color, out_sigma, N);
}

// round 5
// speedup vs baseline: 1.3219x; 1.3219x over previous
#include <cuda_runtime.h>
#include <stdint.h>

// ---------------------------------------------------------------------------
// Fused Instant-NGP forward, round 5:
//  - 3-kernel pipeline: zero counter -> mask+compact (writes trivial outputs
//    for ~35% of points outside the AABB) -> heavy network on active points
//  - heavy kernel = round-3 proven structure (scalar FFMA, float4 __constant__
//    weight broadcasts), with c2 computed in 16-wide quarters and
//    __launch_bounds__(128,5) for 31% occupancy
// ---------------------------------------------------------------------------

#define THASH 524288u
#define THASH_MASK (THASH - 1u)
#define PI2 2654435761u
#define PI3 805459861u

// constant-weight layout (floats, 16B-aligned chunks)
#define OW1 0        // [32,64]
#define OB1 2048
#define OW2 2112     // [64,16]
#define OB2 3136
#define OW3 3152     // [43,64]
#define OB3 5904
#define OW4 5968     // [64,64]
#define OB4 10064
#define OW5 10128    // [64,3]
#define OB5 10320
#define WTOT 10324

__constant__ __align__(16) float cw[WTOT];

// compaction scratch (allocation-free)
__device__ int g_count;
__device__ int g_idx[1 << 20];

__global__ void zero_count_kernel() { g_count = 0; }

__global__ void __launch_bounds__(256)
mask_compact_kernel(const float* __restrict__ gx,
                    float* __restrict__ out_color, float* __restrict__ out_sigma,
                    int N)
{
    int n = blockIdx.x * blockDim.x + threadIdx.x;
    if (n >= N) return;
    float ax = fabsf(gx[3 * n + 0]);
    float ay = fabsf(gx[3 * n + 1]);
    float az = fabsf(gx[3 * n + 2]);
    bool mask = (ax < 1.5f) && (ay < 1.5f) && (az < 1.5f);

    unsigned ball = __ballot_sync(0xFFFFFFFFu, mask);
    int lane = threadIdx.x & 31;
    int base = 0;
    if (lane == 0 && ball) base = atomicAdd(&g_count, __popc(ball));
    base = __shfl_sync(0xFFFFFFFFu, base, 0);
    if (mask) {
        g_idx[base + __popc(ball & ((1u << lane) - 1u))] = n;
    } else {
        out_color[3 * n + 0] = 0.0f;
        out_color[3 * n + 1] = 0.0f;
        out_color[3 * n + 2] = 0.0f;
        out_sigma[n] = -100000.0f;
    }
}

__global__ void __launch_bounds__(128, 5)
ngp_fused_kernel(const float* __restrict__ gx, const float* __restrict__ gd,
                 const float* __restrict__ tables,
                 float* __restrict__ out_color, float* __restrict__ out_sigma)
{
    const float4* cw4 = reinterpret_cast<const float4*>(cw);

    int i = blockIdx.x * blockDim.x + threadIdx.x;
    if (i >= g_count) return;
    int n = g_idx[i];

    // ---- position -> [0,1) coords (mask already true) ----
    float px = gx[3 * n + 0] * (1.0f / 3.0f);
    float py = gx[3 * n + 1] * (1.0f / 3.0f);
    float pz = gx[3 * n + 2] * (1.0f / 3.0f);
    const float HI = 1.0f - 1e-7f;
    float x0 = fminf(fmaxf(px + 0.5f, 0.0f), HI);
    float x1 = fminf(fmaxf(py + 0.5f, 0.0f), HI);
    float x2 = fminf(fmaxf(pz + 0.5f, 0.0f), HI);

    // ---- h1 = b1 + streamed hash-grid features ----
    float h1[64];
    #pragma unroll
    for (int j4 = 0; j4 < 16; j4++) {
        float4 b = cw4[(OB1 >> 2) + j4];
        h1[4*j4+0] = b.x; h1[4*j4+1] = b.y; h1[4*j4+2] = b.z; h1[4*j4+3] = b.w;
    }

    const float resf[16] = {16.f,22.f,30.f,42.f,58.f,80.f,110.f,152.f,
                            210.f,290.f,400.f,552.f,762.f,1052.f,1452.f,2004.f};

    #pragma unroll
    for (int l = 0; l < 16; l++) {
        float res = resf[l];
        float s0 = x0 * res, s1 = x1 * res, s2 = x2 * res;
        float f0 = floorf(s0), f1 = floorf(s1), f2 = floorf(s2);
        float t0 = s0 - f0, t1 = s1 - f1, t2 = s2 - f2;
        float u0 = 1.0f - t0, u1 = 1.0f - t1, u2 = 1.0f - t2;
        uint32_t i0 = (uint32_t)f0, i1 = (uint32_t)f1, i2 = (uint32_t)f2;
        const float2* tab2 = reinterpret_cast<const float2*>(tables) + (size_t)l * (size_t)THASH;
        const float4* tab4 = reinterpret_cast<const float4*>(tab2);

        uint32_t hy0 = i1 * PI2, hy1 = (i1 + 1u) * PI2;
        uint32_t hz0 = i2 * PI3, hz1 = (i2 + 1u) * PI3;
        bool even = (i0 & 1u) == 0u;

        float a0 = 0.0f, a1 = 0.0f;
        #pragma unroll
        for (int cyz = 0; cyz < 4; cyz++) {
            uint32_t hyz = ((cyz & 1) ? hy1 : hy0) ^ ((cyz & 2) ? hz1 : hz0);
            float wyz = ((cyz & 1) ? t1 : u1) * ((cyz & 2) ? t2 : u2);
            uint32_t ia = (i0 ^ hyz) & THASH_MASK;
            float ax, ay, bx, by;
            if (even) {
                float4 g = __ldg(tab4 + (ia >> 1));
                bool lo = (ia & 1u) == 0u;
                ax = lo ? g.x : g.z; ay = lo ? g.y : g.w;
                bx = lo ? g.z : g.x; by = lo ? g.w : g.y;
            } else {
                uint32_t ib = ((i0 + 1u) ^ hyz) & THASH_MASK;
                float2 ga = __ldg(tab2 + ia);
                float2 gb = __ldg(tab2 + ib);
                ax = ga.x; ay = ga.y; bx = gb.x; by = gb.y;
            }
            float wa = wyz * u0, wb = wyz * t0;
            a0 = fmaf(wa, ax, fmaf(wb, bx, a0));
            a1 = fmaf(wa, ay, fmaf(wb, by, a1));
        }

        const int r0 = (OW1 + (2 * l) * 64) >> 2;
        const int r1 = (OW1 + (2 * l + 1) * 64) >> 2;
        #pragma unroll
        for (int j4 = 0; j4 < 16; j4++) {
            float4 u = cw4[r0 + j4];
            float4 v = cw4[r1 + j4];
            h1[4*j4+0] = fmaf(a0, u.x, fmaf(a1, v.x, h1[4*j4+0]));
            h1[4*j4+1] = fmaf(a0, u.y, fmaf(a1, v.y, h1[4*j4+1]));
            h1[4*j4+2] = fmaf(a0, u.z, fmaf(a1, v.z, h1[4*j4+2]));
            h1[4*j4+3] = fmaf(a0, u.w, fmaf(a1, v.w, h1[4*j4+3]));
        }
    }

    // ---- h2 = relu(h1) @ w2 + b2 ----
    float h2[16];
    #pragma unroll
    for (int j4 = 0; j4 < 4; j4++) {
        float4 b = cw4[(OB2 >> 2) + j4];
        h2[4*j4+0] = b.x; h2[4*j4+1] = b.y; h2[4*j4+2] = b.z; h2[4*j4+3] = b.w;
    }
    #pragma unroll
    for (int k = 0; k < 64; k++) {
        float f = fmaxf(h1[k], 0.0f);
        const int rb = (OW2 + k * 16) >> 2;
        #pragma unroll
        for (int j4 = 0; j4 < 4; j4++) {
            float4 u = cw4[rb + j4];
            h2[4*j4+0] = fmaf(f, u.x, h2[4*j4+0]);
            h2[4*j4+1] = fmaf(f, u.y, h2[4*j4+1]);
            h2[4*j4+2] = fmaf(f, u.z, h2[4*j4+2]);
            h2[4*j4+3] = fmaf(f, u.w, h2[4*j4+3]);
        }
    }

    out_sigma[n] = h2[0];

    // ---- c1 = relu(b3 + [dir(27)|h2(16)] @ w3), streamed ----
    float c1[64];
    #pragma unroll
    for (int j4 = 0; j4 < 16; j4++) {
        float4 b = cw4[(OB3 >> 2) + j4];
        c1[4*j4+0] = b.x; c1[4*j4+1] = b.y; c1[4*j4+2] = b.z; c1[4*j4+3] = b.w;
    }

    float dv[3];
    dv[0] = gd[3 * n + 0]; dv[1] = gd[3 * n + 1]; dv[2] = gd[3 * n + 2];

    #define C1_ACC(row, val) do {                                             \
        const int _rb = (OW3 + (row) * 64) >> 2;                              \
        float _f = (val);                                                     \
        _Pragma("unroll")                                                     \
        for (int j4 = 0; j4 < 16; j4++) {                                     \
            float4 u = cw4[_rb + j4];                                         \
            c1[4*j4+0] = fmaf(_f, u.x, c1[4*j4+0]);                           \
            c1[4*j4+1] = fmaf(_f, u.y, c1[4*j4+1]);                           \
            c1[4*j4+2] = fmaf(_f, u.z, c1[4*j4+2]);                           \
            c1[4*j4+3] = fmaf(_f, u.w, c1[4*j4+3]);                           \
        }                                                                     \
    } while (0)

    C1_ACC(0, dv[0]);
    C1_ACC(1, dv[1]);
    C1_ACC(2, dv[2]);
    #pragma unroll
    for (int dim = 0; dim < 3; dim++) {
        #pragma unroll
        for (int f = 0; f < 4; f++) {
            float ang = dv[dim] * (float)(1 << f);
            float s, c;
            __sincosf(ang, &s, &c);
            C1_ACC(3  + dim * 4 + f, s);
            C1_ACC(15 + dim * 4 + f, c);
        }
    }
    #pragma unroll
    for (int j = 0; j < 16; j++) C1_ACC(27 + j, h2[j]);
    #undef C1_ACC

    #pragma unroll
    for (int j = 0; j < 64; j++) c1[j] = fmaxf(c1[j], 0.0f);

    // ---- c2 = relu(c1 @ w4 + b4) in 16-wide quarters, folded into col ----
    float col[3];
    {
        float4 b0 = cw4[OB5 >> 2];
        col[0] = b0.x; col[1] = b0.y; col[2] = b0.z;
    }

    #pragma unroll
    for (int q = 0; q < 4; q++) {
        float c2q[16];
        const int jbase = q * 16;
        #pragma unroll
        for (int j4 = 0; j4 < 4; j4++) {
            float4 b = cw4[((OB4 + jbase) >> 2) + j4];
            c2q[4*j4+0] = b.x; c2q[4*j4+1] = b.y; c2q[4*j4+2] = b.z; c2q[4*j4+3] = b.w;
        }
        #pragma unroll
        for (int k = 0; k < 64; k++) {
            float f = c1[k];
            const int rb = (OW4 + k * 64 + jbase) >> 2;
            #pragma unroll
            for (int j4 = 0; j4 < 4; j4++) {
                float4 u = cw4[rb + j4];
                c2q[4*j4+0] = fmaf(f, u.x, c2q[4*j4+0]);
                c2q[4*j4+1] = fmaf(f, u.y, c2q[4*j4+1]);
                c2q[4*j4+2] = fmaf(f, u.z, c2q[4*j4+2]);
                c2q[4*j4+3] = fmaf(f, u.w, c2q[4*j4+3]);
            }
        }
        #pragma unroll
        for (int k = 0; k < 16; k++) {
            float f = fmaxf(c2q[k], 0.0f);
            const int rw = OW5 + (jbase + k) * 3;
            col[0] = fmaf(f, cw[rw + 0], col[0]);
            col[1] = fmaf(f, cw[rw + 1], col[1]);
            col[2] = fmaf(f, cw[rw + 2], col[2]);
        }
    }

    #pragma unroll
    for (int j = 0; j < 3; j++) {
        float v = 1.0f / (1.0f + __expf(-col[j]));
        out_color[3 * n + j] = v;
    }
}

extern "C" void kernel_launch(void* const* d_in, const int* in_sizes, int n_in,
                              void* d_out, int out_size)
{
    const float* x      = (const float*)d_in[0];
    const float* d      = (const float*)d_in[1];
    const float* tables = (const float*)d_in[2];

    // copy weights into constant memory (D2D, graph-capturable)
    cudaMemcpyToSymbolAsync(cw, d_in[3],  2048 * 4, (size_t)OW1 * 4, cudaMemcpyDeviceToDevice, 0);
    cudaMemcpyToSymbolAsync(cw, d_in[4],    64 * 4, (size_t)OB1 * 4, cudaMemcpyDeviceToDevice, 0);
    cudaMemcpyToSymbolAsync(cw, d_in[5],  1024 * 4, (size_t)OW2 * 4, cudaMemcpyDeviceToDevice, 0);
    cudaMemcpyToSymbolAsync(cw, d_in[6],    16 * 4, (size_t)OB2 * 4, cudaMemcpyDeviceToDevice, 0);
    cudaMemcpyToSymbolAsync(cw, d_in[7],  2752 * 4, (size_t)OW3 * 4, cudaMemcpyDeviceToDevice, 0);
    cudaMemcpyToSymbolAsync(cw, d_in[8],    64 * 4, (size_t)OB3 * 4, cudaMemcpyDeviceToDevice, 0);
    cudaMemcpyToSymbolAsync(cw, d_in[9],  4096 * 4, (size_t)OW4 * 4, cudaMemcpyDeviceToDevice, 0);
    cudaMemcpyToSymbolAsync(cw, d_in[10],   64 * 4, (size_t)OB4 * 4, cudaMemcpyDeviceToDevice, 0);
    cudaMemcpyToSymbolAsync(cw, d_in[11],  192 * 4, (size_t)OW5 * 4, cudaMemcpyDeviceToDevice, 0);
    cudaMemcpyToSymbolAsync(cw, d_in[12],    3 * 4, (size_t)OB5 * 4, cudaMemcpyDeviceToDevice, 0);

    int N = in_sizes[0] / 3;
    float* out       = (float*)d_out;
    float* out_color = out;                   // [N,3]
    float* out_sigma = out + 3 * (size_t)N;   // [N]

    zero_count_kernel<<<1, 1>>>();
    mask_compact_kernel<<<(N + 255) / 256, 256>>>(x, out_color, out_sigma, N);

    int block = 128;
    int grid  = (N + block - 1) / block;   // sized for worst case; tail exits on g_count
    ngp_fused_kernel<<<grid, block>>>(x, d, tables, out_color, out_sigma);
}

// round 7
// speedup vs baseline: 1.6372x; 1.2385x over previous
#include <cuda_runtime.h>
#include <stdint.h>

// ---------------------------------------------------------------------------
// Fused Instant-NGP forward, round 7 (= round 6 resubmitted after infra
// failure; kernel never ran):
//  - 3-kernel pipeline: zero counter -> mask+compact (writes trivial outputs
//    for ~35% points outside AABB) -> heavy network on ~65% active points
//  - heavy kernel is the PROVEN round-3 body at __launch_bounds__(128,4)
//    (128 regs, no spills) with g_idx indirection; mask logic removed
// ---------------------------------------------------------------------------

#define THASH 524288u
#define THASH_MASK (THASH - 1u)
#define PI2 2654435761u
#define PI3 805459861u

// constant-weight layout (floats, 16B-aligned chunks)
#define OW1 0        // [32,64]
#define OB1 2048
#define OW2 2112     // [64,16]
#define OB2 3136
#define OW3 3152     // [43,64]
#define OB3 5904
#define OW4 5968     // [64,64]
#define OB4 10064
#define OW5 10128    // [64,3]
#define OB5 10320
#define WTOT 10324

__constant__ __align__(16) float cw[WTOT];

// compaction scratch (allocation-free)
__device__ int g_count;
__device__ int g_idx[1 << 20];

__global__ void zero_count_kernel() { g_count = 0; }

__global__ void __launch_bounds__(256)
mask_compact_kernel(const float* __restrict__ gx,
                    float* __restrict__ out_color, float* __restrict__ out_sigma,
                    int N)
{
    int n = blockIdx.x * blockDim.x + threadIdx.x;
    if (n >= N) return;
    float ax = fabsf(gx[3 * n + 0]);
    float ay = fabsf(gx[3 * n + 1]);
    float az = fabsf(gx[3 * n + 2]);
    bool mask = (ax < 1.5f) && (ay < 1.5f) && (az < 1.5f);

    unsigned ball = __ballot_sync(0xFFFFFFFFu, mask);
    int lane = threadIdx.x & 31;
    int base = 0;
    if (lane == 0 && ball) base = atomicAdd(&g_count, __popc(ball));
    base = __shfl_sync(0xFFFFFFFFu, base, 0);
    if (mask) {
        g_idx[base + __popc(ball & ((1u << lane) - 1u))] = n;
    } else {
        out_color[3 * n + 0] = 0.0f;
        out_color[3 * n + 1] = 0.0f;
        out_color[3 * n + 2] = 0.0f;
        out_sigma[n] = -100000.0f;
    }
}

__global__ void __launch_bounds__(128, 4)
ngp_fused_kernel(const float* __restrict__ gx, const float* __restrict__ gd,
                 const float* __restrict__ tables,
                 float* __restrict__ out_color, float* __restrict__ out_sigma)
{
    const float4* cw4 = reinterpret_cast<const float4*>(cw);

    int i = blockIdx.x * blockDim.x + threadIdx.x;
    if (i >= g_count) return;
    int n = g_idx[i];

    // ---- position -> [0,1) coords (mask known true) ----
    float px = gx[3 * n + 0] * (1.0f / 3.0f);
    float py = gx[3 * n + 1] * (1.0f / 3.0f);
    float pz = gx[3 * n + 2] * (1.0f / 3.0f);
    const float HI = 1.0f - 1e-7f;
    float x0 = fminf(fmaxf(px + 0.5f, 0.0f), HI);
    float x1 = fminf(fmaxf(py + 0.5f, 0.0f), HI);
    float x2 = fminf(fmaxf(pz + 0.5f, 0.0f), HI);

    // ---- h1 = b1 + streamed hash-grid features ----
    float h1[64];
    #pragma unroll
    for (int j4 = 0; j4 < 16; j4++) {
        float4 b = cw4[(OB1 >> 2) + j4];
        h1[4*j4+0] = b.x; h1[4*j4+1] = b.y; h1[4*j4+2] = b.z; h1[4*j4+3] = b.w;
    }

    const float resf[16] = {16.f,22.f,30.f,42.f,58.f,80.f,110.f,152.f,
                            210.f,290.f,400.f,552.f,762.f,1052.f,1452.f,2004.f};

    #pragma unroll
    for (int l = 0; l < 16; l++) {
        float res = resf[l];
        float s0 = x0 * res, s1 = x1 * res, s2 = x2 * res;
        float f0 = floorf(s0), f1 = floorf(s1), f2 = floorf(s2);
        float t0 = s0 - f0, t1 = s1 - f1, t2 = s2 - f2;
        float u0 = 1.0f - t0, u1 = 1.0f - t1, u2 = 1.0f - t2;
        uint32_t i0 = (uint32_t)f0, i1 = (uint32_t)f1, i2 = (uint32_t)f2;
        const float2* tab2 = reinterpret_cast<const float2*>(tables) + (size_t)l * (size_t)THASH;
        const float4* tab4 = reinterpret_cast<const float4*>(tab2);

        uint32_t hy0 = i1 * PI2, hy1 = (i1 + 1u) * PI2;
        uint32_t hz0 = i2 * PI3, hz1 = (i2 + 1u) * PI3;
        bool even = (i0 & 1u) == 0u;

        float a0 = 0.0f, a1 = 0.0f;
        #pragma unroll
        for (int cyz = 0; cyz < 4; cyz++) {
            uint32_t hyz = ((cyz & 1) ? hy1 : hy0) ^ ((cyz & 2) ? hz1 : hz0);
            float wyz = ((cyz & 1) ? t1 : u1) * ((cyz & 2) ? t2 : u2);
            uint32_t ia = (i0 ^ hyz) & THASH_MASK;
            float ax, ay, bx, by;
            if (even) {
                float4 g = __ldg(tab4 + (ia >> 1));
                bool lo = (ia & 1u) == 0u;
                ax = lo ? g.x : g.z; ay = lo ? g.y : g.w;
                bx = lo ? g.z : g.x; by = lo ? g.w : g.y;
            } else {
                uint32_t ib = ((i0 + 1u) ^ hyz) & THASH_MASK;
                float2 ga = __ldg(tab2 + ia);
                float2 gb = __ldg(tab2 + ib);
                ax = ga.x; ay = ga.y; bx = gb.x; by = gb.y;
            }
            float wa = wyz * u0, wb = wyz * t0;
            a0 = fmaf(wa, ax, fmaf(wb, bx, a0));
            a1 = fmaf(wa, ay, fmaf(wb, by, a1));
        }

        const int r0 = (OW1 + (2 * l) * 64) >> 2;
        const int r1 = (OW1 + (2 * l + 1) * 64) >> 2;
        #pragma unroll
        for (int j4 = 0; j4 < 16; j4++) {
            float4 u = cw4[r0 + j4];
            float4 v = cw4[r1 + j4];
            h1[4*j4+0] = fmaf(a0, u.x, fmaf(a1, v.x, h1[4*j4+0]));
            h1[4*j4+1] = fmaf(a0, u.y, fmaf(a1, v.y, h1[4*j4+1]));
            h1[4*j4+2] = fmaf(a0, u.z, fmaf(a1, v.z, h1[4*j4+2]));
            h1[4*j4+3] = fmaf(a0, u.w, fmaf(a1, v.w, h1[4*j4+3]));
        }
    }

    // ---- h2 = relu(h1) @ w2 + b2 ----
    float h2[16];
    #pragma unroll
    for (int j4 = 0; j4 < 4; j4++) {
        float4 b = cw4[(OB2 >> 2) + j4];
        h2[4*j4+0] = b.x; h2[4*j4+1] = b.y; h2[4*j4+2] = b.z; h2[4*j4+3] = b.w;
    }
    #pragma unroll
    for (int k = 0; k < 64; k++) {
        float f = fmaxf(h1[k], 0.0f);
        const int rb = (OW2 + k * 16) >> 2;
        #pragma unroll
        for (int j4 = 0; j4 < 4; j4++) {
            float4 u = cw4[rb + j4];
            h2[4*j4+0] = fmaf(f, u.x, h2[4*j4+0]);
            h2[4*j4+1] = fmaf(f, u.y, h2[4*j4+1]);
            h2[4*j4+2] = fmaf(f, u.z, h2[4*j4+2]);
            h2[4*j4+3] = fmaf(f, u.w, h2[4*j4+3]);
        }
    }

    out_sigma[n] = h2[0];

    // ---- c1 = relu(b3 + [dir(27)|h2(16)] @ w3), streamed ----
    float c1[64];
    #pragma unroll
    for (int j4 = 0; j4 < 16; j4++) {
        float4 b = cw4[(OB3 >> 2) + j4];
        c1[4*j4+0] = b.x; c1[4*j4+1] = b.y; c1[4*j4+2] = b.z; c1[4*j4+3] = b.w;
    }

    float dv[3];
    dv[0] = gd[3 * n + 0]; dv[1] = gd[3 * n + 1]; dv[2] = gd[3 * n + 2];

    #define C1_ACC(row, val) do {                                             \
        const int _rb = (OW3 + (row) * 64) >> 2;                              \
        float _f = (val);                                                     \
        _Pragma("unroll")                                                     \
        for (int j4 = 0; j4 < 16; j4++) {                                     \
            float4 u = cw4[_rb + j4];                                         \
            c1[4*j4+0] = fmaf(_f, u.x, c1[4*j4+0]);                           \
            c1[4*j4+1] = fmaf(_f, u.y, c1[4*j4+1]);                           \
            c1[4*j4+2] = fmaf(_f, u.z, c1[4*j4+2]);                           \
            c1[4*j4+3] = fmaf(_f, u.w, c1[4*j4+3]);                           \
        }                                                                     \
    } while (0)

    C1_ACC(0, dv[0]);
    C1_ACC(1, dv[1]);
    C1_ACC(2, dv[2]);
    #pragma unroll
    for (int dim = 0; dim < 3; dim++) {
        #pragma unroll
        for (int f = 0; f < 4; f++) {
            float ang = dv[dim] * (float)(1 << f);
            float s, c;
            __sincosf(ang, &s, &c);
            C1_ACC(3  + dim * 4 + f, s);
            C1_ACC(15 + dim * 4 + f, c);
        }
    }
    #pragma unroll
    for (int j = 0; j < 16; j++) C1_ACC(27 + j, h2[j]);
    #undef C1_ACC

    #pragma unroll
    for (int j = 0; j < 64; j++) c1[j] = fmaxf(c1[j], 0.0f);

    // ---- c2 = relu(c1 @ w4 + b4) in 16-wide quarters, folded into col ----
    float col[3];
    {
        float4 b0 = cw4[OB5 >> 2];
        col[0] = b0.x; col[1] = b0.y; col[2] = b0.z;
    }

    #pragma unroll
    for (int q = 0; q < 4; q++) {
        float c2q[16];
        const int jbase = q * 16;
        #pragma unroll
        for (int j4 = 0; j4 < 4; j4++) {
            float4 b = cw4[((OB4 + jbase) >> 2) + j4];
            c2q[4*j4+0] = b.x; c2q[4*j4+1] = b.y; c2q[4*j4+2] = b.z; c2q[4*j4+3] = b.w;
        }
        #pragma unroll
        for (int k = 0; k < 64; k++) {
            float f = c1[k];
            const int rb = (OW4 + k * 64 + jbase) >> 2;
            #pragma unroll
            for (int j4 = 0; j4 < 4; j4++) {
                float4 u = cw4[rb + j4];
                c2q[4*j4+0] = fmaf(f, u.x, c2q[4*j4+0]);
                c2q[4*j4+1] = fmaf(f, u.y, c2q[4*j4+1]);
                c2q[4*j4+2] = fmaf(f, u.z, c2q[4*j4+2]);
                c2q[4*j4+3] = fmaf(f, u.w, c2q[4*j4+3]);
            }
        }
        #pragma unroll
        for (int k = 0; k < 16; k++) {
            float f = fmaxf(c2q[k], 0.0f);
            const int rw = OW5 + (jbase + k) * 3;
            col[0] = fmaf(f, cw[rw + 0], col[0]);
            col[1] = fmaf(f, cw[rw + 1], col[1]);
            col[2] = fmaf(f, cw[rw + 2], col[2]);
        }
    }

    #pragma unroll
    for (int j = 0; j < 3; j++) {
        float v = 1.0f / (1.0f + __expf(-col[j]));
        out_color[3 * n + j] = v;
    }
}

extern "C" void kernel_launch(void* const* d_in, const int* in_sizes, int n_in,
                              void* d_out, int out_size)
{
    const float* x      = (const float*)d_in[0];
    const float* d      = (const float*)d_in[1];
    const float* tables = (const float*)d_in[2];

    // copy weights into constant memory (D2D, graph-capturable)
    cudaMemcpyToSymbolAsync(cw, d_in[3],  2048 * 4, (size_t)OW1 * 4, cudaMemcpyDeviceToDevice, 0);
    cudaMemcpyToSymbolAsync(cw, d_in[4],    64 * 4, (size_t)OB1 * 4, cudaMemcpyDeviceToDevice, 0);
    cudaMemcpyToSymbolAsync(cw, d_in[5],  1024 * 4, (size_t)OW2 * 4, cudaMemcpyDeviceToDevice, 0);
    cudaMemcpyToSymbolAsync(cw, d_in[6],    16 * 4, (size_t)OB2 * 4, cudaMemcpyDeviceToDevice, 0);
    cudaMemcpyToSymbolAsync(cw, d_in[7],  2752 * 4, (size_t)OW3 * 4, cudaMemcpyDeviceToDevice, 0);
    cudaMemcpyToSymbolAsync(cw, d_in[8],    64 * 4, (size_t)OB3 * 4, cudaMemcpyDeviceToDevice, 0);
    cudaMemcpyToSymbolAsync(cw, d_in[9],  4096 * 4, (size_t)OW4 * 4, cudaMemcpyDeviceToDevice, 0);
    cudaMemcpyToSymbolAsync(cw, d_in[10],   64 * 4, (size_t)OB4 * 4, cudaMemcpyDeviceToDevice, 0);
    cudaMemcpyToSymbolAsync(cw, d_in[11],  192 * 4, (size_t)OW5 * 4, cudaMemcpyDeviceToDevice, 0);
    cudaMemcpyToSymbolAsync(cw, d_in[12],    3 * 4, (size_t)OB5 * 4, cudaMemcpyDeviceToDevice, 0);

    int N = in_sizes[0] / 3;
    float* out       = (float*)d_out;
    float* out_color = out;                   // [N,3]
    float* out_sigma = out + 3 * (size_t)N;   // [N]

    zero_count_kernel<<<1, 1>>>();
    mask_compact_kernel<<<(N + 255) / 256, 256>>>(x, out_color, out_sigma, N);

    int block = 128;
    int grid  = (N + block - 1) / block;   // worst case; tail blocks exit on g_count
    ngp_fused_kernel<<<grid, block>>>(x, d, tables, out_color, out_sigma);
}

// round 8
// speedup vs baseline: 2.4981x; 1.5259x over previous
#include <cuda_runtime.h>
#include <stdint.h>

// ---------------------------------------------------------------------------
// Fused Instant-NGP forward, round 8:
//  - 4-kernel pipeline: zero -> mask+compact -> density (hash+MLP1) -> color
//  - density/color split halves per-thread live state (~90 values each) so a
//    102-reg cap (__launch_bounds__(128,5) = 20 warps, 31% occ) fits unspilled
//  - h2[16] passed through SoA scratch g_h2[j][i] (coherent, 1 live reg in B)
// ---------------------------------------------------------------------------

#define THASH 524288u
#define THASH_MASK (THASH - 1u)
#define PI2 2654435761u
#define PI3 805459861u

#define OW1 0        // [32,64]
#define OB1 2048
#define OW2 2112     // [64,16]
#define OB2 3136
#define OW3 3152     // [43,64]
#define OB3 5904
#define OW4 5968     // [64,64]
#define OB4 10064
#define OW5 10128    // [64,3]
#define OB5 10320
#define WTOT 10324

__constant__ __align__(16) float cw[WTOT];

#define NMAX (1 << 20)
__device__ int g_count;
__device__ int g_idx[NMAX];
__device__ float g_h2[16][NMAX];   // SoA: g_h2[j][i]

__global__ void zero_count_kernel() { g_count = 0; }

__global__ void __launch_bounds__(256)
mask_compact_kernel(const float* __restrict__ gx,
                    float* __restrict__ out_color, float* __restrict__ out_sigma,
                    int N)
{
    int n = blockIdx.x * blockDim.x + threadIdx.x;
    if (n >= N) return;
    float ax = fabsf(gx[3 * n + 0]);
    float ay = fabsf(gx[3 * n + 1]);
    float az = fabsf(gx[3 * n + 2]);
    bool mask = (ax < 1.5f) && (ay < 1.5f) && (az < 1.5f);

    unsigned ball = __ballot_sync(0xFFFFFFFFu, mask);
    int lane = threadIdx.x & 31;
    int base = 0;
    if (lane == 0 && ball) base = atomicAdd(&g_count, __popc(ball));
    base = __shfl_sync(0xFFFFFFFFu, base, 0);
    if (mask) {
        g_idx[base + __popc(ball & ((1u << lane) - 1u))] = n;
    } else {
        out_color[3 * n + 0] = 0.0f;
        out_color[3 * n + 1] = 0.0f;
        out_color[3 * n + 2] = 0.0f;
        out_sigma[n] = -100000.0f;
    }
}

// ---------------- Kernel A: hash encode + density MLP -> sigma, g_h2 -------
__global__ void __launch_bounds__(128, 5)
ngp_density_kernel(const float* __restrict__ gx,
                   const float* __restrict__ tables,
                   float* __restrict__ out_sigma)
{
    const float4* cw4 = reinterpret_cast<const float4*>(cw);

    int i = blockIdx.x * blockDim.x + threadIdx.x;
    if (i >= g_count) return;
    int n = g_idx[i];

    float px = gx[3 * n + 0] * (1.0f / 3.0f);
    float py = gx[3 * n + 1] * (1.0f / 3.0f);
    float pz = gx[3 * n + 2] * (1.0f / 3.0f);
    const float HI = 1.0f - 1e-7f;
    float x0 = fminf(fmaxf(px + 0.5f, 0.0f), HI);
    float x1 = fminf(fmaxf(py + 0.5f, 0.0f), HI);
    float x2 = fminf(fmaxf(pz + 0.5f, 0.0f), HI);

    float h1[64];
    #pragma unroll
    for (int j4 = 0; j4 < 16; j4++) {
        float4 b = cw4[(OB1 >> 2) + j4];
        h1[4*j4+0] = b.x; h1[4*j4+1] = b.y; h1[4*j4+2] = b.z; h1[4*j4+3] = b.w;
    }

    const float resf[16] = {16.f,22.f,30.f,42.f,58.f,80.f,110.f,152.f,
                            210.f,290.f,400.f,552.f,762.f,1052.f,1452.f,2004.f};

    #pragma unroll
    for (int l = 0; l < 16; l++) {
        float res = resf[l];
        float s0 = x0 * res, s1 = x1 * res, s2 = x2 * res;
        float f0 = floorf(s0), f1 = floorf(s1), f2 = floorf(s2);
        float t0 = s0 - f0, t1 = s1 - f1, t2 = s2 - f2;
        float u0 = 1.0f - t0, u1 = 1.0f - t1, u2 = 1.0f - t2;
        uint32_t i0 = (uint32_t)f0, i1 = (uint32_t)f1, i2 = (uint32_t)f2;
        const float2* tab2 = reinterpret_cast<const float2*>(tables) + (size_t)l * (size_t)THASH;
        const float4* tab4 = reinterpret_cast<const float4*>(tab2);

        uint32_t hy0 = i1 * PI2, hy1 = (i1 + 1u) * PI2;
        uint32_t hz0 = i2 * PI3, hz1 = (i2 + 1u) * PI3;
        bool even = (i0 & 1u) == 0u;

        float a0 = 0.0f, a1 = 0.0f;
        #pragma unroll
        for (int cyz = 0; cyz < 4; cyz++) {
            uint32_t hyz = ((cyz & 1) ? hy1 : hy0) ^ ((cyz & 2) ? hz1 : hz0);
            float wyz = ((cyz & 1) ? t1 : u1) * ((cyz & 2) ? t2 : u2);
            uint32_t ia = (i0 ^ hyz) & THASH_MASK;
            float ax, ay, bx, by;
            if (even) {
                float4 g = __ldg(tab4 + (ia >> 1));
                bool lo = (ia & 1u) == 0u;
                ax = lo ? g.x : g.z; ay = lo ? g.y : g.w;
                bx = lo ? g.z : g.x; by = lo ? g.w : g.y;
            } else {
                uint32_t ib = ((i0 + 1u) ^ hyz) & THASH_MASK;
                float2 ga = __ldg(tab2 + ia);
                float2 gb = __ldg(tab2 + ib);
                ax = ga.x; ay = ga.y; bx = gb.x; by = gb.y;
            }
            float wa = wyz * u0, wb = wyz * t0;
            a0 = fmaf(wa, ax, fmaf(wb, bx, a0));
            a1 = fmaf(wa, ay, fmaf(wb, by, a1));
        }

        const int r0 = (OW1 + (2 * l) * 64) >> 2;
        const int r1 = (OW1 + (2 * l + 1) * 64) >> 2;
        #pragma unroll
        for (int j4 = 0; j4 < 16; j4++) {
            float4 u = cw4[r0 + j4];
            float4 v = cw4[r1 + j4];
            h1[4*j4+0] = fmaf(a0, u.x, fmaf(a1, v.x, h1[4*j4+0]));
            h1[4*j4+1] = fmaf(a0, u.y, fmaf(a1, v.y, h1[4*j4+1]));
            h1[4*j4+2] = fmaf(a0, u.z, fmaf(a1, v.z, h1[4*j4+2]));
            h1[4*j4+3] = fmaf(a0, u.w, fmaf(a1, v.w, h1[4*j4+3]));
        }
    }

    // h2 = relu(h1) @ w2 + b2
    float h2[16];
    #pragma unroll
    for (int j4 = 0; j4 < 4; j4++) {
        float4 b = cw4[(OB2 >> 2) + j4];
        h2[4*j4+0] = b.x; h2[4*j4+1] = b.y; h2[4*j4+2] = b.z; h2[4*j4+3] = b.w;
    }
    #pragma unroll
    for (int k = 0; k < 64; k++) {
        float f = fmaxf(h1[k], 0.0f);
        const int rb = (OW2 + k * 16) >> 2;
        #pragma unroll
        for (int j4 = 0; j4 < 4; j4++) {
            float4 u = cw4[rb + j4];
            h2[4*j4+0] = fmaf(f, u.x, h2[4*j4+0]);
            h2[4*j4+1] = fmaf(f, u.y, h2[4*j4+1]);
            h2[4*j4+2] = fmaf(f, u.z, h2[4*j4+2]);
            h2[4*j4+3] = fmaf(f, u.w, h2[4*j4+3]);
        }
    }

    out_sigma[n] = h2[0];
    #pragma unroll
    for (int j = 0; j < 16; j++) g_h2[j][i] = h2[j];
}

// ---------------- Kernel B: dir encode + color MLP -> color ----------------
__global__ void __launch_bounds__(128, 5)
ngp_color_kernel(const float* __restrict__ gd,
                 float* __restrict__ out_color)
{
    const float4* cw4 = reinterpret_cast<const float4*>(cw);

    int i = blockIdx.x * blockDim.x + threadIdx.x;
    if (i >= g_count) return;
    int n = g_idx[i];

    float c1[64];
    #pragma unroll
    for (int j4 = 0; j4 < 16; j4++) {
        float4 b = cw4[(OB3 >> 2) + j4];
        c1[4*j4+0] = b.x; c1[4*j4+1] = b.y; c1[4*j4+2] = b.z; c1[4*j4+3] = b.w;
    }

    float dv[3];
    dv[0] = gd[3 * n + 0]; dv[1] = gd[3 * n + 1]; dv[2] = gd[3 * n + 2];

    #define C1_ACC(row, val) do {                                             \
        const int _rb = (OW3 + (row) * 64) >> 2;                              \
        float _f = (val);                                                     \
        _Pragma("unroll")                                                     \
        for (int j4 = 0; j4 < 16; j4++) {                                     \
            float4 u = cw4[_rb + j4];                                         \
            c1[4*j4+0] = fmaf(_f, u.x, c1[4*j4+0]);                           \
            c1[4*j4+1] = fmaf(_f, u.y, c1[4*j4+1]);                           \
            c1[4*j4+2] = fmaf(_f, u.z, c1[4*j4+2]);                           \
            c1[4*j4+3] = fmaf(_f, u.w, c1[4*j4+3]);                           \
        }                                                                     \
    } while (0)

    C1_ACC(0, dv[0]);
    C1_ACC(1, dv[1]);
    C1_ACC(2, dv[2]);
    #pragma unroll
    for (int dim = 0; dim < 3; dim++) {
        #pragma unroll
        for (int f = 0; f < 4; f++) {
            float ang = dv[dim] * (float)(1 << f);
            float s, c;
            __sincosf(ang, &s, &c);
            C1_ACC(3  + dim * 4 + f, s);
            C1_ACC(15 + dim * 4 + f, c);
        }
    }
    // stream h2 from SoA scratch, one value live at a time
    #pragma unroll
    for (int j = 0; j < 16; j++) C1_ACC(27 + j, g_h2[j][i]);
    #undef C1_ACC

    #pragma unroll
    for (int j = 0; j < 64; j++) c1[j] = fmaxf(c1[j], 0.0f);

    float col[3];
    {
        float4 b0 = cw4[OB5 >> 2];
        col[0] = b0.x; col[1] = b0.y; col[2] = b0.z;
    }

    #pragma unroll
    for (int q = 0; q < 4; q++) {
        float c2q[16];
        const int jbase = q * 16;
        #pragma unroll
        for (int j4 = 0; j4 < 4; j4++) {
            float4 b = cw4[((OB4 + jbase) >> 2) + j4];
            c2q[4*j4+0] = b.x; c2q[4*j4+1] = b.y; c2q[4*j4+2] = b.z; c2q[4*j4+3] = b.w;
        }
        #pragma unroll
        for (int k = 0; k < 64; k++) {
            float f = c1[k];
            const int rb = (OW4 + k * 64 + jbase) >> 2;
            #pragma unroll
            for (int j4 = 0; j4 < 4; j4++) {
                float4 u = cw4[rb + j4];
                c2q[4*j4+0] = fmaf(f, u.x, c2q[4*j4+0]);
                c2q[4*j4+1] = fmaf(f, u.y, c2q[4*j4+1]);
                c2q[4*j4+2] = fmaf(f, u.z, c2q[4*j4+2]);
                c2q[4*j4+3] = fmaf(f, u.w, c2q[4*j4+3]);
            }
        }
        #pragma unroll
        for (int k = 0; k < 16; k++) {
            float f = fmaxf(c2q[k], 0.0f);
            const int rw = OW5 + (jbase + k) * 3;
            col[0] = fmaf(f, cw[rw + 0], col[0]);
            col[1] = fmaf(f, cw[rw + 1], col[1]);
            col[2] = fmaf(f, cw[rw + 2], col[2]);
        }
    }

    #pragma unroll
    for (int j = 0; j < 3; j++) {
        float v = 1.0f / (1.0f + __expf(-col[j]));
        out_color[3 * n + j] = v;
    }
}

extern "C" void kernel_launch(void* const* d_in, const int* in_sizes, int n_in,
                              void* d_out, int out_size)
{
    const float* x      = (const float*)d_in[0];
    const float* d      = (const float*)d_in[1];
    const float* tables = (const float*)d_in[2];

    cudaMemcpyToSymbolAsync(cw, d_in[3],  2048 * 4, (size_t)OW1 * 4, cudaMemcpyDeviceToDevice, 0);
    cudaMemcpyToSymbolAsync(cw, d_in[4],    64 * 4, (size_t)OB1 * 4, cudaMemcpyDeviceToDevice, 0);
    cudaMemcpyToSymbolAsync(cw, d_in[5],  1024 * 4, (size_t)OW2 * 4, cudaMemcpyDeviceToDevice, 0);
    cudaMemcpyToSymbolAsync(cw, d_in[6],    16 * 4, (size_t)OB2 * 4, cudaMemcpyDeviceToDevice, 0);
    cudaMemcpyToSymbolAsync(cw, d_in[7],  2752 * 4, (size_t)OW3 * 4, cudaMemcpyDeviceToDevice, 0);
    cudaMemcpyToSymbolAsync(cw, d_in[8],    64 * 4, (size_t)OB3 * 4, cudaMemcpyDeviceToDevice, 0);
    cudaMemcpyToSymbolAsync(cw, d_in[9],  4096 * 4, (size_t)OW4 * 4, cudaMemcpyDeviceToDevice, 0);
    cudaMemcpyToSymbolAsync(cw, d_in[10],   64 * 4, (size_t)OB4 * 4, cudaMemcpyDeviceToDevice, 0);
    cudaMemcpyToSymbolAsync(cw, d_in[11],  192 * 4, (size_t)OW5 * 4, cudaMemcpyDeviceToDevice, 0);
    cudaMemcpyToSymbolAsync(cw, d_in[12],    3 * 4, (size_t)OB5 * 4, cudaMemcpyDeviceToDevice, 0);

    int N = in_sizes[0] / 3;
    float* out       = (float*)d_out;
    float* out_color = out;                   // [N,3]
    float* out_sigma = out + 3 * (size_t)N;   // [N]

    zero_count_kernel<<<1, 1>>>();
    mask_compact_kernel<<<(N + 255) / 256, 256>>>(x, out_color, out_sigma, N);

    int block = 128;
    int grid  = (N + block - 1) / block;   // worst case; tail blocks exit on g_count
    ngp_density_kernel<<<grid, block>>>(x, tables, out_sigma);
    ngp_color_kernel<<<grid, block>>>(d, out_color);
}